// round 1
// baseline (speedup 1.0000x reference)
#include <cuda_runtime.h>
#include <cuda_bf16.h>
#include <math.h>

// DescriptorBuilder: periodic minimum-image descriptors.
// Radial:  q_r[i,k] = sum_j fc(r_ij) * r_ij^k, k=0..8
// Angular (factorized from O(N^3) triple sum to O(N^2) moment sums):
//   q_ang[i,n,0] = S_n^2                     where S_n   = sum_j fc * r^n
//   q_ang[i,n,1] = |V_n|^2                   where V_n   = sum_j fc * r^(n-1) * dr
//   q_ang[i,n,2] = 0.5*(3*||M_n||_F^2 - S_n^2), M_n = sum_j fc * r^(n-2) * dr (x) dr
// Output layout per atom: [q_r(9) | n0:(l0,l1,l2), n1:(...), n2:(...)] = 18 floats.

#define MAXN 1024
#define BLOCK 128
#define NWARP (BLOCK / 32)
#define RCUT 6.0f

__global__ void __launch_bounds__(BLOCK)
desc_kernel(const float* __restrict__ R,
            const float* __restrict__ box,
            float* __restrict__ out, int N)
{
    __shared__ float sS[MAXN][3];     // fractional coordinates
    __shared__ float sB[9];           // box matrix
    __shared__ float red[36][NWARP];  // cross-warp reduction buffer

    const int i = blockIdx.x;
    const int t = threadIdx.x;

    // Load box, compute its inverse (redundantly per thread; 9 elements, cheap).
    float b[9];
#pragma unroll
    for (int k = 0; k < 9; k++) b[k] = box[k];
    if (t < 9) sB[t] = b[t];

    const float det =
        b[0] * (b[4] * b[8] - b[5] * b[7]) -
        b[1] * (b[3] * b[8] - b[5] * b[6]) +
        b[2] * (b[3] * b[7] - b[4] * b[6]);
    const float idet = 1.0f / det;
    float inv[9];
    inv[0] = (b[4] * b[8] - b[5] * b[7]) * idet;
    inv[1] = (b[2] * b[7] - b[1] * b[8]) * idet;
    inv[2] = (b[1] * b[5] - b[2] * b[4]) * idet;
    inv[3] = (b[5] * b[6] - b[3] * b[8]) * idet;
    inv[4] = (b[0] * b[8] - b[2] * b[6]) * idet;
    inv[5] = (b[2] * b[3] - b[0] * b[5]) * idet;
    inv[6] = (b[3] * b[7] - b[4] * b[6]) * idet;
    inv[7] = (b[1] * b[6] - b[0] * b[7]) * idet;
    inv[8] = (b[0] * b[4] - b[1] * b[3]) * idet;

    // Fractional coordinates into shared memory.
    for (int j = t; j < N; j += BLOCK) {
        float x = R[3 * j + 0], y = R[3 * j + 1], z = R[3 * j + 2];
        sS[j][0] = inv[0] * x + inv[1] * y + inv[2] * z;
        sS[j][1] = inv[3] * x + inv[4] * y + inv[5] * z;
        sS[j][2] = inv[6] * x + inv[7] * y + inv[8] * z;
    }
    __syncthreads();

    const float si0 = sS[i][0], si1 = sS[i][1], si2 = sS[i][2];

    // Accumulators: [0..8] radial; [9..17] V_n (3x3); [18..35] M_n (3x6 sym)
    float acc[36];
#pragma unroll
    for (int k = 0; k < 36; k++) acc[k] = 0.0f;

    const float PI = 3.14159265358979323846f;

    for (int j = t; j < N; j += BLOCK) {
        if (j == i) continue;
        float d0 = si0 - sS[j][0];
        float d1 = si1 - sS[j][1];
        float d2 = si2 - sS[j][2];
        d0 -= rintf(d0);  // minimum image (round-half-even, matches jnp.round)
        d1 -= rintf(d1);
        d2 -= rintf(d2);
        float dx = sB[0] * d0 + sB[1] * d1 + sB[2] * d2 + 1e-16f;
        float dy = sB[3] * d0 + sB[4] * d1 + sB[5] * d2 + 1e-16f;
        float dz = sB[6] * d0 + sB[7] * d1 + sB[8] * d2 + 1e-16f;
        float r2 = dx * dx + dy * dy + dz * dz;
        float r = sqrtf(r2);
        if (r >= RCUT) continue;  // fc is exactly 0 at/beyond cutoff

        float fc = 0.5f * (cosf(PI * (r * (1.0f / RCUT))) + 1.0f);

        // Radial: fc * r^k, k = 0..8
        float p = fc;
#pragma unroll
        for (int k = 0; k < 9; k++) { acc[k] += p; p *= r; }

        float invr = 1.0f / r;
        float wv = fc * invr;          // n=0 vector weight: fc * r^(-1)
        float wm = fc * invr * invr;   // n=0 tensor weight: fc * r^(-2)
        float xx = dx * dx, xy = dx * dy, xz = dx * dz;
        float yy = dy * dy, yz = dy * dz, zz = dz * dz;
#pragma unroll
        for (int n = 0; n < 3; n++) {
            acc[9 + 3 * n + 0] += wv * dx;
            acc[9 + 3 * n + 1] += wv * dy;
            acc[9 + 3 * n + 2] += wv * dz;
            acc[18 + 6 * n + 0] += wm * xx;
            acc[18 + 6 * n + 1] += wm * xy;
            acc[18 + 6 * n + 2] += wm * xz;
            acc[18 + 6 * n + 3] += wm * yy;
            acc[18 + 6 * n + 4] += wm * yz;
            acc[18 + 6 * n + 5] += wm * zz;
            wv *= r;
            wm *= r;
        }
    }

    // Warp-level tree reduction of all 36 accumulators.
#pragma unroll
    for (int k = 0; k < 36; k++) {
        float v = acc[k];
#pragma unroll
        for (int o = 16; o > 0; o >>= 1) v += __shfl_xor_sync(0xffffffffu, v, o);
        acc[k] = v;
    }
    const int warp = t >> 5, lane = t & 31;
    if (lane == 0) {
#pragma unroll
        for (int k = 0; k < 36; k++) red[k][warp] = acc[k];
    }
    __syncthreads();

    if (t == 0) {
        float tot[36];
#pragma unroll
        for (int k = 0; k < 36; k++) {
            float v = 0.0f;
#pragma unroll
            for (int w = 0; w < NWARP; w++) v += red[k][w];
            tot[k] = v;
        }
        float* o = out + (size_t)i * 18;
#pragma unroll
        for (int k = 0; k < 9; k++) o[k] = tot[k];
#pragma unroll
        for (int n = 0; n < 3; n++) {
            float s  = tot[n];  // S_n == radial moment for k=n
            float vx = tot[9 + 3 * n + 0];
            float vy = tot[9 + 3 * n + 1];
            float vz = tot[9 + 3 * n + 2];
            float m0 = tot[18 + 6 * n + 0], m1 = tot[18 + 6 * n + 1];
            float m2 = tot[18 + 6 * n + 2], m3 = tot[18 + 6 * n + 3];
            float m4 = tot[18 + 6 * n + 4], m5 = tot[18 + 6 * n + 5];
            float frob = m0 * m0 + m3 * m3 + m5 * m5 +
                         2.0f * (m1 * m1 + m2 * m2 + m4 * m4);
            o[9 + 3 * n + 0] = s * s;
            o[9 + 3 * n + 1] = vx * vx + vy * vy + vz * vz;
            o[9 + 3 * n + 2] = 0.5f * (3.0f * frob - s * s);
        }
    }
}

extern "C" void kernel_launch(void* const* d_in, const int* in_sizes, int n_in,
                              void* d_out, int out_size) {
    const float* R   = (const float*)d_in[0];   // [N,3] fp32
    // d_in[1] = Z (int32), unused by the reference math
    const float* box = (const float*)d_in[2];   // [3,3] fp32
    float* out = (float*)d_out;                 // [N,18] fp32
    const int N = in_sizes[0] / 3;
    desc_kernel<<<N, BLOCK>>>(R, box, out, N);
}

// round 2
// speedup vs baseline: 1.0332x; 1.0332x over previous
#include <cuda_runtime.h>
#include <cuda_bf16.h>
#include <math.h>

// DescriptorBuilder: periodic minimum-image descriptors (O(N^2) factorized).
// Radial:  q_r[i,k] = sum_j fc(r_ij) * r_ij^k, k=0..8
// Angular: q_ang[i,n,0] = S_n^2, S_n = sum_j fc r^n
//          q_ang[i,n,1] = |V_n|^2, V_n = sum_j fc r^(n-1) dr
//          q_ang[i,n,2] = 0.5*(3*||M_n||_F^2 - S_n^2), M_n = sum_j fc r^(n-2) dr(x)dr
// One WARP per atom i; 2 warps (2 atoms) per 64-thread block -> single wave,
// single warp-butterfly reduction, no cross-warp/shared reduction stage.

#define BLOCK 64
#define MAXN 512
#define RCUT 6.0f

__global__ void __launch_bounds__(BLOCK)
desc_kernel(const float* __restrict__ R,
            const float* __restrict__ box,
            float* __restrict__ out, int N)
{
    __shared__ float s0[MAXN], s1[MAXN], s2[MAXN];

    const int t    = threadIdx.x;
    const int lane = t & 31;
    const int warp = t >> 5;
    const int i    = blockIdx.x * 2 + warp;   // atom this warp owns

    // Box in registers + inverse (redundant per thread; ~40 cheap ops).
    float b[9];
#pragma unroll
    for (int k = 0; k < 9; k++) b[k] = __ldg(box + k);

    const float det =
        b[0] * (b[4] * b[8] - b[5] * b[7]) -
        b[1] * (b[3] * b[8] - b[5] * b[6]) +
        b[2] * (b[3] * b[7] - b[4] * b[6]);
    const float idet = 1.0f / det;
    float inv[9];
    inv[0] = (b[4] * b[8] - b[5] * b[7]) * idet;
    inv[1] = (b[2] * b[7] - b[1] * b[8]) * idet;
    inv[2] = (b[1] * b[5] - b[2] * b[4]) * idet;
    inv[3] = (b[5] * b[6] - b[3] * b[8]) * idet;
    inv[4] = (b[0] * b[8] - b[2] * b[6]) * idet;
    inv[5] = (b[2] * b[3] - b[0] * b[5]) * idet;
    inv[6] = (b[3] * b[7] - b[4] * b[6]) * idet;
    inv[7] = (b[1] * b[6] - b[0] * b[7]) * idet;
    inv[8] = (b[0] * b[4] - b[1] * b[3]) * idet;

    // Fractional coordinates into shared (3 separate arrays: conflict-free LDS).
    for (int j = t; j < N; j += BLOCK) {
        float x = __ldg(R + 3 * j + 0);
        float y = __ldg(R + 3 * j + 1);
        float z = __ldg(R + 3 * j + 2);
        s0[j] = inv[0] * x + inv[1] * y + inv[2] * z;
        s1[j] = inv[3] * x + inv[4] * y + inv[5] * z;
        s2[j] = inv[6] * x + inv[7] * y + inv[8] * z;
    }
    __syncthreads();

    if (i >= N) return;

    const float si0 = s0[i], si1 = s1[i], si2 = s2[i];
    const float PI_OVER_RC = 3.14159265358979323846f / RCUT;

    // Accumulators: [0..8] radial; [9..17] V_n; [18..35] M_n (sym 3x3, 6 each)
    float acc[36];
#pragma unroll
    for (int k = 0; k < 36; k++) acc[k] = 0.0f;

#pragma unroll 2
    for (int j = lane; j < N; j += 32) {
        if (j == i) continue;
        float d0 = si0 - s0[j];
        float d1 = si1 - s1[j];
        float d2 = si2 - s2[j];
        d0 -= rintf(d0);   // minimum image (round-half-even = jnp.round)
        d1 -= rintf(d1);
        d2 -= rintf(d2);
        float dx = b[0] * d0 + b[1] * d1 + b[2] * d2 + 1e-16f;
        float dy = b[3] * d0 + b[4] * d1 + b[5] * d2 + 1e-16f;
        float dz = b[6] * d0 + b[7] * d1 + b[8] * d2 + 1e-16f;
        float r2 = dx * dx + dy * dy + dz * dz;
        float invr = rsqrtf(r2);
        float r = r2 * invr;
        if (r >= RCUT) continue;   // fc exactly 0 there

        float fc = 0.5f * __cosf(r * PI_OVER_RC) + 0.5f;

        // Radial moments fc * r^k, k = 0..8
        float p = fc;
#pragma unroll
        for (int k = 0; k < 9; k++) { acc[k] += p; p *= r; }

        float wv = fc * invr;          // n=0 vector weight fc*r^-1
        float wm = wv * invr;          // n=0 tensor weight fc*r^-2
        float xx = dx * dx, xy = dx * dy, xz = dx * dz;
        float yy = dy * dy, yz = dy * dz, zz = dz * dz;
#pragma unroll
        for (int n = 0; n < 3; n++) {
            acc[9 + 3 * n + 0] += wv * dx;
            acc[9 + 3 * n + 1] += wv * dy;
            acc[9 + 3 * n + 2] += wv * dz;
            acc[18 + 6 * n + 0] += wm * xx;
            acc[18 + 6 * n + 1] += wm * xy;
            acc[18 + 6 * n + 2] += wm * xz;
            acc[18 + 6 * n + 3] += wm * yy;
            acc[18 + 6 * n + 4] += wm * yz;
            acc[18 + 6 * n + 5] += wm * zz;
            wv *= r;
            wm *= r;
        }
    }

    // Single warp butterfly reduction over all 36 accumulators.
#pragma unroll
    for (int k = 0; k < 36; k++) {
        float v = acc[k];
#pragma unroll
        for (int o = 16; o > 0; o >>= 1) v += __shfl_xor_sync(0xffffffffu, v, o);
        acc[k] = v;
    }

    if (lane == 0) {
        float* o = out + (size_t)i * 18;
#pragma unroll
        for (int k = 0; k < 9; k++) o[k] = acc[k];
#pragma unroll
        for (int n = 0; n < 3; n++) {
            float s  = acc[n];   // S_n equals radial moment k=n
            float vx = acc[9 + 3 * n + 0];
            float vy = acc[9 + 3 * n + 1];
            float vz = acc[9 + 3 * n + 2];
            float m0 = acc[18 + 6 * n + 0], m1 = acc[18 + 6 * n + 1];
            float m2 = acc[18 + 6 * n + 2], m3 = acc[18 + 6 * n + 3];
            float m4 = acc[18 + 6 * n + 4], m5 = acc[18 + 6 * n + 5];
            float frob = m0 * m0 + m3 * m3 + m5 * m5 +
                         2.0f * (m1 * m1 + m2 * m2 + m4 * m4);
            o[9 + 3 * n + 0] = s * s;
            o[9 + 3 * n + 1] = vx * vx + vy * vy + vz * vz;
            o[9 + 3 * n + 2] = 0.5f * (3.0f * frob - s * s);
        }
    }
}

extern "C" void kernel_launch(void* const* d_in, const int* in_sizes, int n_in,
                              void* d_out, int out_size) {
    const float* R   = (const float*)d_in[0];   // [N,3] fp32
    // d_in[1] = Z (int32), unused by the reference math
    const float* box = (const float*)d_in[2];   // [3,3] fp32
    float* out = (float*)d_out;                 // [N,18] fp32
    const int N = in_sizes[0] / 3;
    const int blocks = (N + 1) / 2;             // one warp per atom, 2 warps/block
    desc_kernel<<<blocks, BLOCK>>>(R, box, out, N);
}

// round 3
// speedup vs baseline: 1.3659x; 1.3220x over previous
#include <cuda_runtime.h>
#include <cuda_bf16.h>
#include <math.h>

// DescriptorBuilder: periodic minimum-image descriptors (O(N^2) factorized).
// Radial:  q_r[i,k] = sum_j fc(r_ij) * r_ij^k, k=0..8
// Angular: q_ang[i,n,0] = S_n^2, S_n = sum_j fc r^n
//          q_ang[i,n,1] = |V_n|^2, V_n = sum_j fc r^(n-1) dr
//          q_ang[i,n,2] = 0.5*(3*||M_n||_F^2 - S_n^2), M_n = sum_j fc r^(n-2) dr(x)dr
//
// 2 warps per atom (split j-range), 2 atoms per 128-thread block, 96 blocks
// = one wave on 148 SMs with all 4 SMSPs busy. Butterfly reduce within warp,
// smem combine across the warp pair, epilogue distributed over 18 lanes.

#define BLOCK 128
#define MAXN 512
#define RCUT 6.0f

__global__ void __launch_bounds__(BLOCK)
desc_kernel(const float* __restrict__ R,
            const float* __restrict__ box,
            float* __restrict__ out, int N)
{
    __shared__ float s0[MAXN], s1[MAXN], s2[MAXN];
    __shared__ float sred[2][36];   // partial sums from the "sub==1" warp of each atom

    const int t    = threadIdx.x;
    const int lane = t & 31;
    const int warp = t >> 5;        // 0..3
    const int a    = warp >> 1;     // atom slot within block (0/1)
    const int sub  = warp & 1;      // which half of j-range
    const int i    = blockIdx.x * 2 + a;
    const bool valid = (i < N);

    // Box + inverse in registers (redundant per thread, cheap).
    float b[9];
#pragma unroll
    for (int k = 0; k < 9; k++) b[k] = __ldg(box + k);

    const bool diag = (b[1] == 0.f && b[2] == 0.f && b[3] == 0.f &&
                       b[5] == 0.f && b[6] == 0.f && b[7] == 0.f);

    const float det =
        b[0] * (b[4] * b[8] - b[5] * b[7]) -
        b[1] * (b[3] * b[8] - b[5] * b[6]) +
        b[2] * (b[3] * b[7] - b[4] * b[6]);
    const float idet = 1.0f / det;
    float inv[9];
    inv[0] = (b[4] * b[8] - b[5] * b[7]) * idet;
    inv[1] = (b[2] * b[7] - b[1] * b[8]) * idet;
    inv[2] = (b[1] * b[5] - b[2] * b[4]) * idet;
    inv[3] = (b[5] * b[6] - b[3] * b[8]) * idet;
    inv[4] = (b[0] * b[8] - b[2] * b[6]) * idet;
    inv[5] = (b[2] * b[3] - b[0] * b[5]) * idet;
    inv[6] = (b[3] * b[7] - b[4] * b[6]) * idet;
    inv[7] = (b[1] * b[6] - b[0] * b[7]) * idet;
    inv[8] = (b[0] * b[4] - b[1] * b[3]) * idet;

    // Fractional coordinates into shared (3 arrays: conflict-free LDS).
    if (diag) {
        const float i0 = inv[0], i4 = inv[4], i8 = inv[8];
        for (int j = t; j < N; j += BLOCK) {
            s0[j] = i0 * __ldg(R + 3 * j + 0);
            s1[j] = i4 * __ldg(R + 3 * j + 1);
            s2[j] = i8 * __ldg(R + 3 * j + 2);
        }
    } else {
        for (int j = t; j < N; j += BLOCK) {
            float x = __ldg(R + 3 * j + 0);
            float y = __ldg(R + 3 * j + 1);
            float z = __ldg(R + 3 * j + 2);
            s0[j] = inv[0] * x + inv[1] * y + inv[2] * z;
            s1[j] = inv[3] * x + inv[4] * y + inv[5] * z;
            s2[j] = inv[6] * x + inv[7] * y + inv[8] * z;
        }
    }
    __syncthreads();

    const float PI_OVER_RC = 3.14159265358979323846f / RCUT;

    // Accumulators: [0..8] radial (S_n = acc[n]); [9..17] V_n; [18..35] M_n.
    float acc[36];
#pragma unroll
    for (int k = 0; k < 36; k++) acc[k] = 0.0f;

    if (valid) {
        const float si0 = s0[i], si1 = s1[i], si2 = s2[i];
        const float b0 = b[0], b4 = b[4], b8 = b[8];

        for (int j = lane + 32 * sub; j < N; j += 64) {
            if (j == i) continue;
            float d0 = si0 - s0[j];
            float d1 = si1 - s1[j];
            float d2 = si2 - s2[j];
            d0 -= rintf(d0);   // minimum image (round-half-even = jnp.round)
            d1 -= rintf(d1);
            d2 -= rintf(d2);
            float dx, dy, dz;
            if (diag) {
                dx = b0 * d0; dy = b4 * d1; dz = b8 * d2;
            } else {
                dx = b[0] * d0 + b[1] * d1 + b[2] * d2;
                dy = b[3] * d0 + b[4] * d1 + b[5] * d2;
                dz = b[6] * d0 + b[7] * d1 + b[8] * d2;
            }
            float r2 = dx * dx + dy * dy + dz * dz;
            float invr = rsqrtf(r2);
            float r = r2 * invr;
            if (r >= RCUT) continue;   // fc exactly 0 there

            float fc = 0.5f * __cosf(r * PI_OVER_RC) + 0.5f;

            // Radial moments fc * r^k, k = 0..8 (log-depth powers)
            float rr2 = r * r;
            float rr3 = rr2 * r;
            float rr4 = rr2 * rr2;
            float fcr4 = fc * rr4;
            acc[0] += fc;
            acc[1] += fc * r;
            acc[2] += fc * rr2;
            acc[3] += fc * rr3;
            acc[4] += fcr4;
            acc[5] += fcr4 * r;
            acc[6] += fcr4 * rr2;
            acc[7] += fcr4 * rr3;
            acc[8] += fcr4 * rr4;

            // Angular moment weights: wv_n = fc r^(n-1), wm_n = fc r^(n-2)
            float wv0 = fc * invr;     // = wm1
            float wv2 = fc * r;
            float wm0 = wv0 * invr;
            float xx = dx * dx, xy = dx * dy, xz = dx * dz;
            float yy = dy * dy, yz = dy * dz, zz = dz * dz;

            acc[9]  += wv0 * dx;  acc[10] += wv0 * dy;  acc[11] += wv0 * dz;
            acc[12] += fc  * dx;  acc[13] += fc  * dy;  acc[14] += fc  * dz;
            acc[15] += wv2 * dx;  acc[16] += wv2 * dy;  acc[17] += wv2 * dz;

            acc[18] += wm0 * xx;  acc[19] += wm0 * xy;  acc[20] += wm0 * xz;
            acc[21] += wm0 * yy;  acc[22] += wm0 * yz;  acc[23] += wm0 * zz;
            acc[24] += wv0 * xx;  acc[25] += wv0 * xy;  acc[26] += wv0 * xz;
            acc[27] += wv0 * yy;  acc[28] += wv0 * yz;  acc[29] += wv0 * zz;
            acc[30] += fc  * xx;  acc[31] += fc  * xy;  acc[32] += fc  * xz;
            acc[33] += fc  * yy;  acc[34] += fc  * yz;  acc[35] += fc  * zz;
        }

        // Warp butterfly: afterwards EVERY lane holds all 36 sums.
#pragma unroll
        for (int k = 0; k < 36; k++) {
            float v = acc[k];
#pragma unroll
            for (int o = 16; o > 0; o >>= 1) v += __shfl_xor_sync(0xffffffffu, v, o);
            acc[k] = v;
        }
    }

    // Cross-warp combine: sub==1 warp publishes its 36 sums.
    if (sub == 1) {
        if (lane < 36) sred[a][lane] = acc[lane];
        if (lane < 4)  sred[a][32 + lane] = acc[32 + lane];
    }
    __syncthreads();

    if (valid && sub == 0 && lane < 18) {
#pragma unroll
        for (int k = 0; k < 36; k++) acc[k] += sred[a][k];   // broadcast LDS

        float* o = out + (size_t)i * 18;
        float val;
        if (lane < 9) {
            val = acc[lane];
        } else {
            int idx = lane - 9;
            int n = idx / 3;
            int l = idx - 3 * n;
            float s = acc[n];
            if (l == 0) {
                val = s * s;
            } else if (l == 1) {
                float vx = acc[9 + 3 * n], vy = acc[10 + 3 * n], vz = acc[11 + 3 * n];
                val = vx * vx + vy * vy + vz * vz;
            } else {
                float m0 = acc[18 + 6 * n], m1 = acc[19 + 6 * n], m2 = acc[20 + 6 * n];
                float m3 = acc[21 + 6 * n], m4 = acc[22 + 6 * n], m5 = acc[23 + 6 * n];
                float frob = m0 * m0 + m3 * m3 + m5 * m5 +
                             2.0f * (m1 * m1 + m2 * m2 + m4 * m4);
                val = 0.5f * (3.0f * frob - s * s);
            }
        }
        o[lane] = val;
    }
}

extern "C" void kernel_launch(void* const* d_in, const int* in_sizes, int n_in,
                              void* d_out, int out_size) {
    const float* R   = (const float*)d_in[0];   // [N,3] fp32
    // d_in[1] = Z (int32), unused by the reference math
    const float* box = (const float*)d_in[2];   // [3,3] fp32
    float* out = (float*)d_out;                 // [N,18] fp32
    const int N = in_sizes[0] / 3;
    const int blocks = (N + 1) / 2;             // 2 atoms per block
    desc_kernel<<<blocks, BLOCK>>>(R, box, out, N);
}